// round 8
// baseline (speedup 1.0000x reference)
#include <cuda_runtime.h>
#include <cstdint>

// Involution2d on GB300 (sm_103 base ISA). B=4, C=256, H=W=64, G=16, K=7, PAD=3.
// Stage 1 = mma.sync.m16n8k8 tf32 (taps padded 49->56), stage 2 = fp32 conv.
// Block = (b, h-pair, gq): 512 threads, 2 output rows, 4 groups.

#define CH 256
#define HH 64
#define WW 64
#define KT 7
#define KK 49
#define CC 64                  // channels per chunk
#define NCHUNK 4
#define TAPS 224               // 4 groups * 56 padded taps
#define PX 128                 // pixels per block (2 rows)
#define KROW 132               // k_s row stride, 132%32=4 -> conflict-free

#define XBUF_F (CC * PX)       // 8192 floats
#define WBUF_F (CC * TAPS)     // 14336 floats (cg-major kappa layout)
#define SMEM_BYTES ((2 * XBUF_F + 2 * WBUF_F) * 4)   // 180224

// g_wt2: [cgGlobal 32][gq 4][n 224][8], where the 8 = (unit<<1)|half with
//   unit = (k8 & 3) ^ ((n >> 2) & 3)   (anti-conflict XOR baked in)
//   half = k8 >> 2,  k8 = channel & 7
__device__ float g_wt2[32 * 4 * TAPS * 8];

// ---------------- helpers ----------------
__device__ __forceinline__ uint32_t f2tf32u(float x) {
    uint32_t u;
    asm("cvt.rn.tf32.f32 %0, %1;" : "=r"(u) : "f"(x));
    return u;
}
__device__ __forceinline__ void cp16(float* dst, const float* src) {
    unsigned sa = (unsigned)__cvta_generic_to_shared(dst);
    asm volatile("cp.async.cg.shared.global [%0], [%1], 16;" :: "r"(sa), "l"(src));
}
__device__ __forceinline__ void cp_commit() { asm volatile("cp.async.commit_group;"); }
__device__ __forceinline__ void cp_wait1()  { asm volatile("cp.async.wait_group 1;"); }
__device__ __forceinline__ void cp_wait0()  { asm volatile("cp.async.wait_group 0;"); }

__device__ __forceinline__ void mma8(float* c, const uint32_t* a, const uint32_t* b) {
    asm volatile(
        "mma.sync.aligned.m16n8k8.row.col.f32.tf32.tf32.f32 "
        "{%0,%1,%2,%3}, {%4,%5,%6,%7}, {%8,%9}, {%0,%1,%2,%3};"
        : "+f"(c[0]), "+f"(c[1]), "+f"(c[2]), "+f"(c[3])
        : "r"(a[0]), "r"(a[1]), "r"(a[2]), "r"(a[3]), "r"(b[0]), "r"(b[1]));
}

// ---------------- w repack: tf32 round + kappa-interleave + bake XOR ----------------
// block = (cgGlobal*4 + gq), 224 threads (one per n)
__global__ void wt_pack_kernel(const float* __restrict__ wk) {
    const int blk = blockIdx.x;
    const int cgG = blk >> 2, gq = blk & 3;
    const int n = threadIdx.x;              // 0..223
    const int grp = n / 56, kk = n % 56;
    const int c0 = cgG * 8;
    float* dst = g_wt2 + ((size_t)blk * TAPS + n) * 8;
    if (kk < KK) {
        const float* src = wk + (size_t)((gq * 4 + grp) * KK + kk) * CH + c0;
        #pragma unroll
        for (int k8 = 0; k8 < 8; ++k8) {
            const int unit = (k8 & 3) ^ ((n >> 2) & 3);
            const int half = k8 >> 2;
            dst[unit * 2 + half] = __uint_as_float(f2tf32u(src[k8]));
        }
    } else {
        #pragma unroll
        for (int i = 0; i < 8; ++i) dst[i] = 0.0f;
    }
}

// ---------------- fused main kernel ----------------
__global__ __launch_bounds__(512, 1)
void invo_main_kernel(const float* __restrict__ x,
                      const float* __restrict__ bk,
                      float* __restrict__ out) {
    extern __shared__ float sm[];
    float* xbuf0 = sm;
    float* xbuf1 = sm + XBUF_F;
    float* wbuf0 = sm + 2 * XBUF_F;
    float* wbuf1 = sm + 2 * XBUF_F + WBUF_F;
    float* k_s   = sm;                      // [slot 196][KROW], aliased after stage 1

    const int t  = threadIdx.x;
    const int rb = blockIdx.x;
    const int b  = rb >> 5;
    const int h  = (rb & 31) * 2;           // rows h, h+1
    const int gq = blockIdx.y;

    // ---- chunk loader ----
    // x_s[k][px128]: elem (k,px) at k*128 + (px ^ 8*(k&3))
    // w_s[cg][n][8]: direct copy of g_wt2 slab (kappa layout, XOR baked)
    auto load_chunk = [&](int chunk, int pb) {
        const int c0 = chunk * CC;
        float* xb = pb ? xbuf1 : xbuf0;
        float* wb = pb ? wbuf1 : wbuf0;
        #pragma unroll
        for (int i = 0; i < 4; ++i) {                 // 2048 cp16
            const int u = t + 512 * i;
            const int k = u >> 5;
            const int p4 = (u & 31) << 2;
            cp16(xb + k * PX + (p4 ^ (8 * (k & 3))),
                 x + ((size_t)(b * CH + c0 + k)) * 4096 + h * 64 + p4);
        }
        #pragma unroll
        for (int i = 0; i < 7; ++i) {                 // 3584 cp16
            const int u = t + 512 * i;
            const int cg = u / 448;
            const int r = u - cg * 448;               // 0..447 float4 units
            cp16(wb + cg * (TAPS * 8) + r * 4,
                 g_wt2 + ((size_t)((chunk * 8 + cg) * 4 + gq) * TAPS) * 8 + r * 4);
        }
        cp_commit();
    };

    // ---- Stage 1: mma.sync tf32, 16 warps, warp tile m32 x n56 ----
    const int wid = t >> 5, lane = t & 31;
    const int la = lane & 3, gid = lane >> 2;
    const int mq = wid & 3, nq = wid >> 2;
    const int m0w = mq * 32;                // pixel base (0..96)
    const int n0w = nq * 56;                // tap base = group nq
    const int sw = 8 * la;

    float acc[2][7][4];
    #pragma unroll
    for (int mt = 0; mt < 2; ++mt)
        #pragma unroll
        for (int nt = 0; nt < 7; ++nt)
            #pragma unroll
            for (int i = 0; i < 4; ++i) acc[mt][nt][i] = 0.0f;

    load_chunk(0, 0);
    for (int ch = 0; ch < NCHUNK; ++ch) {
        const int pb = ch & 1;
        if (ch + 1 < NCHUNK) { load_chunk(ch + 1, pb ^ 1); cp_wait1(); }
        else                 { cp_wait0(); }
        __syncthreads();

        const float* xb = pb ? xbuf1 : xbuf0;
        const float* wb = pb ? wbuf1 : wbuf0;

        #pragma unroll
        for (int ks = 0; ks < 8; ++ks) {
            const int kb = ks * 8;
            uint32_t af[2][4];
            #pragma unroll
            for (int mt = 0; mt < 2; ++mt) {
                const int rm = m0w + mt * 16;
                const int r0 = (rm + gid) ^ sw;
                const int r1 = (rm + 8 + gid) ^ sw;
                af[mt][0] = f2tf32u(xb[(kb + la) * PX + r0]);
                af[mt][1] = f2tf32u(xb[(kb + la) * PX + r1]);
                af[mt][2] = f2tf32u(xb[(kb + la + 4) * PX + r0]);
                af[mt][3] = f2tf32u(xb[(kb + la + 4) * PX + r1]);
            }
            const float* wrow = wb + ks * (TAPS * 8);
            #pragma unroll
            for (int nt = 0; nt < 7; ++nt) {
                const int cn = n0w + nt * 8 + gid;
                const int unit = la ^ ((cn >> 2) & 3);
                const float2 bv = *(const float2*)(wrow + cn * 8 + unit * 2);
                uint32_t bf[2] = {__float_as_uint(bv.x), __float_as_uint(bv.y)};
                mma8(acc[0][nt], af[0], bf);
                mma8(acc[1][nt], af[1], bf);
            }
        }
        __syncthreads();
    }

    // ---- epilogue: bias add, write k_s[slot = nq*49+kk][px] ----
    {
        const int px0 = m0w + gid;
        #pragma unroll
        for (int nt = 0; nt < 7; ++nt) {
            const int kk = nt * 8 + la * 2;
            if (kk < KK) {
                const float bias = bk[(gq * 4 + nq) * KK + kk];
                const int s = nq * KK + kk;
                k_s[s * KROW + px0]      = acc[0][nt][0] + bias;
                k_s[s * KROW + px0 + 8]  = acc[0][nt][2] + bias;
                k_s[s * KROW + px0 + 16] = acc[1][nt][0] + bias;
                k_s[s * KROW + px0 + 24] = acc[1][nt][2] + bias;
            }
            if (kk + 1 < KK) {
                const float bias1 = bk[(gq * 4 + nq) * KK + kk + 1];
                const int s1 = nq * KK + kk + 1;
                k_s[s1 * KROW + px0]      = acc[0][nt][1] + bias1;
                k_s[s1 * KROW + px0 + 8]  = acc[0][nt][3] + bias1;
                k_s[s1 * KROW + px0 + 16] = acc[1][nt][1] + bias1;
                k_s[s1 * KROW + px0 + 24] = acc[1][nt][3] + bias1;
            }
        }
    }
    __syncthreads();

    // ---- Stage 2: apply per-pixel 7x7 kernels (fp32) ----
    const int pxg  = t & 15, w0 = pxg << 2;
    const int q    = (t >> 4) & 15;
    const int grp2 = q >> 2, chq = q & 3;
    const int hrow = t >> 8;
    const int hout = h + hrow;

    float o[4][4];
    #pragma unroll
    for (int m = 0; m < 4; ++m)
        #pragma unroll
        for (int pi = 0; pi < 4; ++pi) o[m][pi] = 0.0f;

    #pragma unroll
    for (int kh = 0; kh < KT; ++kh) {
        const int hh = hout + kh - 3;
        if ((unsigned)hh >= (unsigned)HH) continue;

        float4 kvf[KT];
        #pragma unroll
        for (int kw = 0; kw < KT; ++kw)
            kvf[kw] = *(const float4*)&k_s[(grp2 * KK + kh * KT + kw) * KROW + hrow * 64 + w0];

        #pragma unroll
        for (int m = 0; m < 4; ++m) {
            const int c = gq * 64 + grp2 * 16 + chq + (m << 2);
            const float* xr = x + ((size_t)(b * CH + c) * HH + hh) * WW;
            const float4 A = (pxg >= 1)  ? *(const float4*)(xr + w0 - 4)
                                         : make_float4(0.f, 0.f, 0.f, 0.f);
            const float4 Bv = *(const float4*)(xr + w0);
            const float4 Cc = (pxg <= 14) ? *(const float4*)(xr + w0 + 4)
                                          : make_float4(0.f, 0.f, 0.f, 0.f);
            const float xv[10] = {A.y, A.z, A.w, Bv.x, Bv.y, Bv.z, Bv.w, Cc.x, Cc.y, Cc.z};
            #pragma unroll
            for (int kw = 0; kw < KT; ++kw) {
                o[m][0] += xv[kw]     * kvf[kw].x;
                o[m][1] += xv[kw + 1] * kvf[kw].y;
                o[m][2] += xv[kw + 2] * kvf[kw].z;
                o[m][3] += xv[kw + 3] * kvf[kw].w;
            }
        }
    }

    #pragma unroll
    for (int m = 0; m < 4; ++m) {
        const int c = gq * 64 + grp2 * 16 + chq + (m << 2);
        *reinterpret_cast<float4*>(out + ((size_t)(b * CH + c) * HH + hout) * WW + w0) =
            make_float4(o[m][0], o[m][1], o[m][2], o[m][3]);
    }
}

extern "C" void kernel_launch(void* const* d_in, const int* in_sizes, int n_in,
                              void* d_out, int out_size) {
    const float* x  = (const float*)d_in[0];
    const float* wk = (const float*)d_in[1];
    const float* bk = (const float*)d_in[2];
    float* out      = (float*)d_out;

    wt_pack_kernel<<<128, TAPS>>>(wk);

    cudaFuncSetAttribute(invo_main_kernel,
                         cudaFuncAttributeMaxDynamicSharedMemorySize, SMEM_BYTES);
    dim3 grid(4 * 32, 4);               // (b*hpair, gq) = (128, 4) = 512 blocks
    invo_main_kernel<<<grid, 512, SMEM_BYTES>>>(x, bk, out);
}

// round 9
// speedup vs baseline: 1.1581x; 1.1581x over previous
#include <cuda_runtime.h>
#include <cstdint>

// Involution2d on GB300 (sm_103 base ISA). B=4, C=256, H=W=64, G=16, K=7, PAD=3.
// Stage 1 = mma.sync.m16n8k8 tf32 (taps padded 49->56), stage 2 = fp32 conv.
// Block = (b, h-pair, gq-pair): 256 threads, 2 output rows, 2 groups, 2 blocks/SM.

#define CH 256
#define HH 64
#define WW 64
#define KT 7
#define KK 49
#define CC 32                  // channels per chunk
#define NCHUNK 8
#define TAPS 112               // 2 groups * 56 padded taps
#define PX 128                 // pixels per block (2 rows)
#define KROW 132               // k_s row stride, 132%32=4 -> conflict-free

#define XBUF_F (CC * PX)       // 4096 floats
#define WBUF_F (CC * TAPS)     // 3584 floats (octet-major kappa layout)
#define SMEM_BYTES ((2 * XBUF_F + 2 * WBUF_F) * 4)   // 61440

// g_wt2: [cgOctet 32][gqp 8][n 112][8], 8 = (unit<<1)|half with
//   unit = (k8 & 3) ^ ((n >> 2) & 3)   (anti-conflict XOR baked in)
//   half = k8 >> 2,  k8 = channel & 7,  n = grp*56 + kk
__device__ float g_wt2[32 * 8 * TAPS * 8];

// ---------------- helpers ----------------
__device__ __forceinline__ uint32_t f2tf32u(float x) {
    uint32_t u;
    asm("cvt.rn.tf32.f32 %0, %1;" : "=r"(u) : "f"(x));
    return u;
}
__device__ __forceinline__ void cp16(float* dst, const float* src) {
    unsigned sa = (unsigned)__cvta_generic_to_shared(dst);
    asm volatile("cp.async.cg.shared.global [%0], [%1], 16;" :: "r"(sa), "l"(src));
}
__device__ __forceinline__ void cp_commit() { asm volatile("cp.async.commit_group;"); }
__device__ __forceinline__ void cp_wait1()  { asm volatile("cp.async.wait_group 1;"); }
__device__ __forceinline__ void cp_wait0()  { asm volatile("cp.async.wait_group 0;"); }

__device__ __forceinline__ void mma8(float* c, const uint32_t* a, const uint32_t* b) {
    asm volatile(
        "mma.sync.aligned.m16n8k8.row.col.f32.tf32.tf32.f32 "
        "{%0,%1,%2,%3}, {%4,%5,%6,%7}, {%8,%9}, {%0,%1,%2,%3};"
        : "+f"(c[0]), "+f"(c[1]), "+f"(c[2]), "+f"(c[3])
        : "r"(a[0]), "r"(a[1]), "r"(a[2]), "r"(a[3]), "r"(b[0]), "r"(b[1]));
}

// ---------------- w repack: tf32 round + kappa-interleave + bake XOR ----------------
// block = cgOctet*8 + gqp, 112 threads (one per n)
__global__ void wt_pack_kernel(const float* __restrict__ wk) {
    const int blk = blockIdx.x;
    const int cgO = blk >> 3, gqp = blk & 7;
    const int n = threadIdx.x;              // 0..111
    const int grp = n / 56, kk = n % 56;
    const int c0 = cgO * 8;
    float* dst = g_wt2 + ((size_t)blk * TAPS + n) * 8;
    if (kk < KK) {
        const float* src = wk + (size_t)((gqp * 2 + grp) * KK + kk) * CH + c0;
        #pragma unroll
        for (int k8 = 0; k8 < 8; ++k8) {
            const int unit = (k8 & 3) ^ ((n >> 2) & 3);
            const int half = k8 >> 2;
            dst[unit * 2 + half] = __uint_as_float(f2tf32u(src[k8]));
        }
    } else {
        #pragma unroll
        for (int i = 0; i < 8; ++i) dst[i] = 0.0f;
    }
}

// ---------------- fused main kernel ----------------
__global__ __launch_bounds__(256, 2)
void invo_main_kernel(const float* __restrict__ x,
                      const float* __restrict__ bk,
                      float* __restrict__ out) {
    extern __shared__ float sm[];
    float* xbuf0 = sm;
    float* xbuf1 = sm + XBUF_F;
    float* wbuf0 = sm + 2 * XBUF_F;
    float* wbuf1 = sm + 2 * XBUF_F + WBUF_F;
    float* k_s   = sm;                      // [slot 98][KROW], aliased after stage 1

    const int t   = threadIdx.x;
    const int rb  = blockIdx.x;
    const int b   = rb >> 5;
    const int h   = (rb & 31) * 2;          // rows h, h+1
    const int gqp = blockIdx.y;             // group pair 0..7

    // ---- chunk loader ----
    auto load_chunk = [&](int chunk, int pb) {
        const int c0 = chunk * CC;
        float* xb = pb ? xbuf1 : xbuf0;
        float* wb = pb ? wbuf1 : wbuf0;
        #pragma unroll
        for (int i = 0; i < 4; ++i) {                 // 1024 cp16
            const int u = t + 256 * i;
            const int k = u >> 5;
            const int p4 = (u & 31) << 2;
            cp16(xb + k * PX + (p4 ^ (8 * (k & 3))),
                 x + ((size_t)(b * CH + c0 + k)) * 4096 + h * 64 + p4);
        }
        #pragma unroll
        for (int i = 0; i < 4; ++i) {                 // 896 cp16
            const int u = t + 256 * i;
            if (u < 896) {
                const int cg = u / 224;               // channel octet within chunk
                const int r = u - cg * 224;           // float4 unit within slab
                cp16(wb + cg * (TAPS * 8) + r * 4,
                     g_wt2 + ((size_t)((chunk * 4 + cg) * 8 + gqp) * TAPS) * 8 + r * 4);
            }
        }
        cp_commit();
    };

    // ---- Stage 1: mma.sync tf32, 8 warps, warp tile m32 x n56 ----
    const int wid = t >> 5, lane = t & 31;
    const int la = lane & 3, gid = lane >> 2;
    const int mq = wid & 3, nq = wid >> 2;  // nq 0..1
    const int m0w = mq * 32;
    const int n0w = nq * 56;
    const int sw = 8 * la;

    float acc[2][7][4];
    #pragma unroll
    for (int mt = 0; mt < 2; ++mt)
        #pragma unroll
        for (int nt = 0; nt < 7; ++nt)
            #pragma unroll
            for (int i = 0; i < 4; ++i) acc[mt][nt][i] = 0.0f;

    load_chunk(0, 0);
    for (int ch = 0; ch < NCHUNK; ++ch) {
        const int pb = ch & 1;
        if (ch + 1 < NCHUNK) { load_chunk(ch + 1, pb ^ 1); cp_wait1(); }
        else                 { cp_wait0(); }
        __syncthreads();

        const float* xb = pb ? xbuf1 : xbuf0;
        const float* wb = pb ? wbuf1 : wbuf0;

        #pragma unroll
        for (int ks = 0; ks < 4; ++ks) {
            const int kb = ks * 8;
            uint32_t af[2][4];
            #pragma unroll
            for (int mt = 0; mt < 2; ++mt) {
                const int rm = m0w + mt * 16;
                const int r0 = (rm + gid) ^ sw;
                const int r1 = (rm + 8 + gid) ^ sw;
                af[mt][0] = f2tf32u(xb[(kb + la) * PX + r0]);
                af[mt][1] = f2tf32u(xb[(kb + la) * PX + r1]);
                af[mt][2] = f2tf32u(xb[(kb + la + 4) * PX + r0]);
                af[mt][3] = f2tf32u(xb[(kb + la + 4) * PX + r1]);
            }
            const float* wrow = wb + ks * (TAPS * 8);
            #pragma unroll
            for (int nt = 0; nt < 7; ++nt) {
                const int cn = n0w + nt * 8 + gid;
                const int unit = la ^ ((cn >> 2) & 3);
                const float2 bv = *(const float2*)(wrow + cn * 8 + unit * 2);
                uint32_t bf[2] = {__float_as_uint(bv.x), __float_as_uint(bv.y)};
                mma8(acc[0][nt], af[0], bf);
                mma8(acc[1][nt], af[1], bf);
            }
        }
        __syncthreads();
    }

    // ---- epilogue: bias add, write k_s[slot = nq*49+kk][px] ----
    {
        const int px0 = m0w + gid;
        #pragma unroll
        for (int nt = 0; nt < 7; ++nt) {
            const int kk = nt * 8 + la * 2;
            if (kk < KK) {
                const float bias = bk[(gqp * 2 + nq) * KK + kk];
                const int s = nq * KK + kk;
                k_s[s * KROW + px0]      = acc[0][nt][0] + bias;
                k_s[s * KROW + px0 + 8]  = acc[0][nt][2] + bias;
                k_s[s * KROW + px0 + 16] = acc[1][nt][0] + bias;
                k_s[s * KROW + px0 + 24] = acc[1][nt][2] + bias;
            }
            if (kk + 1 < KK) {
                const float bias1 = bk[(gqp * 2 + nq) * KK + kk + 1];
                const int s1 = nq * KK + kk + 1;
                k_s[s1 * KROW + px0]      = acc[0][nt][1] + bias1;
                k_s[s1 * KROW + px0 + 8]  = acc[0][nt][3] + bias1;
                k_s[s1 * KROW + px0 + 16] = acc[1][nt][1] + bias1;
                k_s[s1 * KROW + px0 + 24] = acc[1][nt][3] + bias1;
            }
        }
    }
    __syncthreads();

    // ---- Stage 2: apply per-pixel 7x7 kernels (fp32) ----
    const int pxg  = t & 15, w0 = pxg << 2;
    const int chq  = (t >> 4) & 3;
    const int grp2 = (t >> 6) & 1;
    const int hrow = t >> 7;
    const int hout = h + hrow;

    float o[4][4];
    #pragma unroll
    for (int m = 0; m < 4; ++m)
        #pragma unroll
        for (int pi = 0; pi < 4; ++pi) o[m][pi] = 0.0f;

    #pragma unroll
    for (int kh = 0; kh < KT; ++kh) {
        const int hh = hout + kh - 3;
        if ((unsigned)hh >= (unsigned)HH) continue;

        float4 kvf[KT];
        #pragma unroll
        for (int kw = 0; kw < KT; ++kw)
            kvf[kw] = *(const float4*)&k_s[(grp2 * KK + kh * KT + kw) * KROW + hrow * 64 + w0];

        #pragma unroll
        for (int m = 0; m < 4; ++m) {
            const int c = gqp * 32 + grp2 * 16 + chq + (m << 2);
            const float* xr = x + ((size_t)(b * CH + c) * HH + hh) * WW;
            const float4 A = (pxg >= 1)  ? *(const float4*)(xr + w0 - 4)
                                         : make_float4(0.f, 0.f, 0.f, 0.f);
            const float4 Bv = *(const float4*)(xr + w0);
            const float4 Cc = (pxg <= 14) ? *(const float4*)(xr + w0 + 4)
                                          : make_float4(0.f, 0.f, 0.f, 0.f);
            const float xv[10] = {A.y, A.z, A.w, Bv.x, Bv.y, Bv.z, Bv.w, Cc.x, Cc.y, Cc.z};
            #pragma unroll
            for (int kw = 0; kw < KT; ++kw) {
                o[m][0] += xv[kw]     * kvf[kw].x;
                o[m][1] += xv[kw + 1] * kvf[kw].y;
                o[m][2] += xv[kw + 2] * kvf[kw].z;
                o[m][3] += xv[kw + 3] * kvf[kw].w;
            }
        }
    }

    #pragma unroll
    for (int m = 0; m < 4; ++m) {
        const int c = gqp * 32 + grp2 * 16 + chq + (m << 2);
        *reinterpret_cast<float4*>(out + ((size_t)(b * CH + c) * HH + hout) * WW + w0) =
            make_float4(o[m][0], o[m][1], o[m][2], o[m][3]);
    }
}

extern "C" void kernel_launch(void* const* d_in, const int* in_sizes, int n_in,
                              void* d_out, int out_size) {
    const float* x  = (const float*)d_in[0];
    const float* wk = (const float*)d_in[1];
    const float* bk = (const float*)d_in[2];
    float* out      = (float*)d_out;

    wt_pack_kernel<<<256, TAPS>>>(wk);

    cudaFuncSetAttribute(invo_main_kernel,
                         cudaFuncAttributeMaxDynamicSharedMemorySize, SMEM_BYTES);
    dim3 grid(4 * 32, 8);               // (b*hpair, gq-pair) = (128, 8) = 1024 blocks
    invo_main_kernel<<<grid, 256, SMEM_BYTES>>>(x, bk, out);
}